// round 17
// baseline (speedup 1.0000x reference)
#include <cuda_runtime.h>
#include <cuda_pipeline.h>
#include <cstdint>

#define NN 256   // nodes
#define FF 256   // feature dim
#define BB 32    // batch
#define EE 8192  // edges
#define SPAN_CAP 6144   // local CSR entries per half (actual ~4100 + pads)

// ---------------------------------------------------------------------------
// Single fused kernel. Block = (f-tile of 4 floats) x (half of dst range).
// Grid 128 = 64 f-tiles x 2 halves. 1024 threads (32 warps/SM, RF-capped).
//
// Phase 0: build this half's dst-CSR in SMEM (overlapped with x cp.async).
// Phase 1: warp owns 4 CONSECUTIVE dst nodes => contiguous padded CSR span.
// Flat 32-edge chunks over the span (100% fill), double-buffered per-lane
// cp.async W gathers. After wait, a FIXUP pass folds c into the staged W
// (each lane scales its own slot once). CONSUME: per edge = LDS src +
// LDS wc + LDS.128 x + 4 FMA; node-boundary flushes via cheap compare.
// ---------------------------------------------------------------------------
__global__ void __launch_bounds__(1024, 1)
ep_fused_kernel(const float* __restrict__ x,     // [B, N, F]
                const float* __restrict__ W,     // [N, N, F]
                const float* __restrict__ phase, // [N, N]
                const int* __restrict__ src32,
                const int* __restrict__ dst32,
                float* __restrict__ out) {       // [B, N, F]
    extern __shared__ char s_raw[];
    float4* s_x  = reinterpret_cast<float4*>(s_raw);               // 128KB
    int2*  s_csr = reinterpret_cast<int2*>(s_raw + NN * BB * 16);  // 48KB
    __shared__ float4 s_wr[32][2][32];  // per-warp double-buffered W staging (32KB)
    __shared__ int    s_rp[128 + 1];
    __shared__ int    s_cnt[128];
    __shared__ int    s_off[128];
    __shared__ int    s_bad;

    const int bx     = blockIdx.x;               // 0..127
    const int f0     = (bx >> 1) * 4;
    const int n_base = (bx & 1) * 128;
    const int t      = threadIdx.x;
    const int warp   = t >> 5;
    const int lane   = t & 31;

    // ---- kick x-tile staging (async; overlaps the CSR build below) ----
    for (int i = t; i < NN * BB; i += 1024) {
        const int s = i >> 5;
        const int b = i & 31;
        __pipeline_memcpy_async(&s_x[i],
                                x + (size_t)(b * NN + s) * FF + f0,
                                sizeof(float4));
    }
    __pipeline_commit();

    // ---- parallel int64-LE detection ----
    if (t == 0) s_bad = 0;
    if (t < 128) s_cnt[t] = 0;
    __syncthreads();
    if (t < 64) {
        const int lo = dst32[2 * t];
        const int hi = dst32[2 * t + 1];
        if (hi != 0 || lo < 0 || lo >= NN) s_bad = 1;
    }
    __syncthreads();
    const int stride = s_bad ? 1 : 2;

    // ---- count this half's rows ----
    for (int e = t; e < EE; e += 1024) {
        const int d = dst32[e * stride];
        const int nl = d - n_base;
        if ((unsigned)nl < 128u) atomicAdd(&s_cnt[nl], 1);
    }
    __syncthreads();

    // ---- warp 0: exclusive scan of 128 padded counts ----
    if (warp == 0) {
        const int i0 = lane * 4;
        const int c0 = (s_cnt[i0 + 0] + 7) & ~7;
        const int c1 = (s_cnt[i0 + 1] + 7) & ~7;
        const int c2 = (s_cnt[i0 + 2] + 7) & ~7;
        const int c3 = (s_cnt[i0 + 3] + 7) & ~7;
        const int tot = c0 + c1 + c2 + c3;
        int pre = tot;
        for (int off = 1; off < 32; off <<= 1) {
            const int v = __shfl_up_sync(0xFFFFFFFFu, pre, off);
            if (lane >= off) pre += v;
        }
        const int base = pre - tot;
        s_rp[i0 + 0] = base;
        s_rp[i0 + 1] = base + c0;
        s_rp[i0 + 2] = base + c0 + c1;
        s_rp[i0 + 3] = base + c0 + c1 + c2;
        if (lane == 31) s_rp[128] = base + tot;
    }
    __syncthreads();

    // ---- init cursors; zero only the pad slots ----
    if (t < 128) {
        s_off[t] = s_rp[t];
        const int fe = s_rp[t] + s_cnt[t];
        const int re = s_rp[t + 1];
        for (int i = fe; i < re && i < SPAN_CAP; i++)
            s_csr[i] = make_int2(0, 0);
    }
    __syncthreads();

    // ---- fill: weight = cos(phase)/32 ----
    for (int e = t; e < EE; e += 1024) {
        const int d = dst32[e * stride];
        const int nl = d - n_base;
        if ((unsigned)nl < 128u) {
            const int s = src32[e * stride];
            const int pos = atomicAdd(&s_off[nl], 1);
            if (pos < SPAN_CAP) {
                const float c = cosf(phase[s * NN + d]) * (1.0f / 32.0f);
                s_csr[pos] = make_int2(s, __float_as_int(c));
            }
        }
    }
    __pipeline_wait_prior(0);   // drain x staging
    __syncthreads();

    // ---- phase 1: flat-chunk, double-buffered, fixup-folded compute ----
    const int w4 = warp << 2;           // first local node of this warp
    const int b0 = s_rp[w4];
    const int b1 = s_rp[w4 + 1];
    const int b2 = s_rp[w4 + 2];
    const int b3 = s_rp[w4 + 3];
    const int b4 = s_rp[w4 + 4];
    const int nch = (b4 - b0 + 31) >> 5;   // full 32-edge chunks (span mult 8)

    float c0reg = 0.f, c1reg = 0.f;

    // issue chunk ci into buffer buf; stash this lane's c in the right reg.
    auto issue = [&](int ci, int buf) {
        const int base = b0 + (ci << 5);
        float cv = 0.f;
        if (base < b4) {
            const int cnt = min(32, b4 - base);
            if (lane < cnt) {
                const int ia = base + lane;
                const int2 e = s_csr[ia];
                const int k = (ia >= b1) + (ia >= b2) + (ia >= b3);
                const float* p = W + (size_t)(n_base + w4 + k) * FF + f0
                                   + (size_t)e.x * (NN * FF);
                __pipeline_memcpy_async(&s_wr[warp][buf][lane], p,
                                        sizeof(float4));
                cv = __int_as_float(e.y);
            }
        }
        if (buf) c1reg = cv; else c0reg = cv;
        __pipeline_commit();
    };

    issue(0, 0);
    issue(1, 1);

    int curn = 0;          // node being accumulated (0..3)
    int nb   = b1;         // its end boundary (abs index)
    float4 a0 = make_float4(0.f, 0.f, 0.f, 0.f);
    float4 a1 = make_float4(0.f, 0.f, 0.f, 0.f);

    for (int ci = 0; ci < nch; ci++) {
        const int buf  = ci & 1;
        const int base = b0 + (ci << 5);
        const int cnt  = min(32, b4 - base);   // multiple of 8

        __pipeline_wait_prior(1);              // this chunk's copies done
        // fixup: fold c into staged W (own slot, conflict-free)
        {
            const float cc = buf ? c1reg : c0reg;
            if (lane < cnt) {
                const float4 wv = s_wr[warp][buf][lane];
                s_wr[warp][buf][lane] =
                    make_float4(wv.x * cc, wv.y * cc, wv.z * cc, wv.w * cc);
            }
        }
        __syncwarp();

        const float4* wb = s_wr[warp][buf];
        for (int j = 0; j < cnt; j += 4) {
            const int i = base + j;
            // node boundary flush (boundaries are mult-of-8 => land on groups)
            while (i >= nb && curn < 3) {
                const int n = n_base + w4 + curn;
                *reinterpret_cast<float4*>(
                    out + (size_t)(lane * NN + n) * FF + f0) =
                    make_float4(a0.x + a1.x, a0.y + a1.y,
                                a0.z + a1.z, a0.w + a1.w);
                a0 = make_float4(0.f, 0.f, 0.f, 0.f);
                a1 = make_float4(0.f, 0.f, 0.f, 0.f);
                ++curn;
                nb = s_rp[w4 + curn + 1];
            }
#pragma unroll
            for (int u = 0; u < 4; ++u) {
                const int    sv = s_csr[i + u].x;    // broadcast LDS
                const float4 wc = wb[j + u];         // broadcast LDS
                const float4 xv = s_x[(sv << 5) + lane];
                if (u & 1) {
                    a1.x = fmaf(xv.x, wc.x, a1.x);
                    a1.y = fmaf(xv.y, wc.y, a1.y);
                    a1.z = fmaf(xv.z, wc.z, a1.z);
                    a1.w = fmaf(xv.w, wc.w, a1.w);
                } else {
                    a0.x = fmaf(xv.x, wc.x, a0.x);
                    a0.y = fmaf(xv.y, wc.y, a0.y);
                    a0.z = fmaf(xv.z, wc.z, a0.z);
                    a0.w = fmaf(xv.w, wc.w, a0.w);
                }
            }
        }
        __syncwarp();                          // buf free before reissue
        issue(ci + 2, buf);
    }

    // final flushes (covers trailing/empty nodes)
    for (;;) {
        const int n = n_base + w4 + curn;
        *reinterpret_cast<float4*>(
            out + (size_t)(lane * NN + n) * FF + f0) =
            make_float4(a0.x + a1.x, a0.y + a1.y,
                        a0.z + a1.z, a0.w + a1.w);
        if (curn == 3) break;
        ++curn;
        a0 = make_float4(0.f, 0.f, 0.f, 0.f);
        a1 = make_float4(0.f, 0.f, 0.f, 0.f);
    }
}

// ---------------------------------------------------------------------------
extern "C" void kernel_launch(void* const* d_in, const int* in_sizes, int n_in,
                              void* d_out, int out_size) {
    const float* x     = (const float*)d_in[0];
    const float* W     = (const float*)d_in[1];
    const float* phase = (const float*)d_in[2];
    const int*   src   = (const int*)d_in[3];
    const int*   dst   = (const int*)d_in[4];
    float*       out   = (float*)d_out;

    // dynamic: 128KB x-tile + 48KB local CSR (static ~34KB incl. staging).
    const int smem = NN * BB * 16 + SPAN_CAP * 8;
    cudaFuncSetAttribute(ep_fused_kernel,
                         cudaFuncAttributeMaxDynamicSharedMemorySize, smem);

    ep_fused_kernel<<<128, 1024, smem>>>(x, W, phase, src, dst, out);
}